// round 16
// baseline (speedup 1.0000x reference)
#include <cuda_runtime.h>
#include <cuda_fp16.h>

#define BB 256
#define SS 512
#define FF 64
#define HH 128
#define NT 256

typedef unsigned long long ull;

// Weights packed along k: g_wk[gate][kp][j] = half2(W[FF+2kp][j], W[FF+2kp+1][j])
// Gates i,f,o are PRE-SCALED by 0.5 (exact) so sigmoid args need no runtime mul.
__device__ __align__(16) __half2 g_wk[4 * 64 * 128];
__device__ __align__(16) float4  g_xw4[64 * 128];    // (xk,j) -> (.5wi,.5wf,.5wo,wg) fp32
__device__ __align__(16) float4  g_bias4[128];       // (.5bi,.5bf,.5bo,bg)

__global__ void pack_kernel(const float* __restrict__ Wi, const float* __restrict__ bi,
                            const float* __restrict__ Wf, const float* __restrict__ bf,
                            const float* __restrict__ Wo, const float* __restrict__ bo,
                            const float* __restrict__ Wg, const float* __restrict__ bg) {
    const int kp = blockIdx.x;       // 0..63 (k-pair)
    const int t  = threadIdx.x;
    const int j  = t & 127;
    const int pr = t >> 7;
    const int d0 = FF + 2 * kp, d1 = FF + 2 * kp + 1;
    if (pr == 0) {
        g_wk[0 * 8192 + kp * 128 + j] = __floats2half2_rn(0.5f * Wi[d0 * HH + j], 0.5f * Wi[d1 * HH + j]);
        g_wk[1 * 8192 + kp * 128 + j] = __floats2half2_rn(0.5f * Wf[d0 * HH + j], 0.5f * Wf[d1 * HH + j]);
        g_xw4[kp * 128 + j] = make_float4(0.5f * Wi[kp * HH + j], 0.5f * Wf[kp * HH + j],
                                          0.5f * Wo[kp * HH + j], Wg[kp * HH + j]);
    } else {
        g_wk[2 * 8192 + kp * 128 + j] = __floats2half2_rn(0.5f * Wo[d0 * HH + j], 0.5f * Wo[d1 * HH + j]);
        g_wk[3 * 8192 + kp * 128 + j] = __floats2half2_rn(Wg[d0 * HH + j], Wg[d1 * HH + j]);
        if (kp == 0) g_bias4[j] = make_float4(0.5f * bi[j], 0.5f * bf[j], 0.5f * bo[j], bg[j]);
    }
}

__device__ __forceinline__ float fast_ex2(float a) { float r; asm("ex2.approx.f32 %0, %1;" : "=f"(r) : "f"(a)); return r; }
__device__ __forceinline__ float fast_rcp(float a) { float r; asm("rcp.approx.f32 %0, %1;" : "=f"(r) : "f"(a)); return r; }
__device__ __forceinline__ float tanh_ex(float x) { return fmaf(-2.0f, fast_rcp(1.0f + fast_ex2(2.8853900817779268f * x)), 1.0f); }

__device__ __forceinline__ __half2 u2h2(unsigned u) { __half2 r; *reinterpret_cast<unsigned*>(&r) = u; return r; }
__device__ __forceinline__ unsigned h2u(__half2 h) { return *reinterpret_cast<unsigned*>(&h); }
__device__ __forceinline__ __half2 tanh_h2(__half2 a) {
    unsigned r, x = h2u(a);
    asm("tanh.approx.f16x2 %0, %1;" : "=r"(r) : "r"(x));
    return u2h2(r);
}
// half2(lo a + hi a, lo b + hi b): 2 PRMT (alu pipe) + 1 HADD2
__device__ __forceinline__ __half2 pairsum(__half2 a, __half2 b) {
    const unsigned lo = __byte_perm(h2u(a), h2u(b), 0x5410);
    const unsigned hi = __byte_perm(h2u(a), h2u(b), 0x7632);
    return __hadd2(u2h2(lo), u2h2(hi));
}

// packed dual-fp32 ops (Blackwell f32x2 path; carriers are 64-bit regs)
#define FMA2(d, a, b, c) asm("fma.rn.f32x2 %0, %1, %2, %3;" : "=l"(d) : "l"(a), "l"(b), "l"(c))
#define MUL2(d, a, b)    asm("mul.rn.f32x2 %0, %1, %2;"     : "=l"(d) : "l"(a), "l"(b))
#define ADD2(d, a, b)    asm("add.rn.f32x2 %0, %1, %2;"     : "=l"(d) : "l"(a), "l"(b))

// Smem: [0,131072) float4 s_xw | [131072,+1088) half s_h16[2 buf] | [132160,+2048) float4 s_xf[2][64] = (x0,x0,x1,x1)
#define SMH_OFF 131072
#define SXF_OFF 132160
#define SMEM_BYTES (132160 + 2048)

__global__ void __launch_bounds__(NT, 1)
clstm_kernel(const float* __restrict__ x, const float* __restrict__ td, float* __restrict__ out) {
    extern __shared__ char sm[];
    __half* s_h16 = reinterpret_cast<__half*>(sm + SMH_OFF);
    float2* s_xf2 = reinterpret_cast<float2*>(sm + SXF_OFF);   // [2 buf][64 k][2 b] splats
    const ulonglong2* s_xwu = reinterpret_cast<const ulonglong2*>(sm);        // (wi,wf),(wo,wg)
    const ulonglong2* s_xfu = reinterpret_cast<const ulonglong2*>(sm + SXF_OFF); // (x0,x0),(x1,x1)

    const int t    = threadIdx.x;
    const int lane = t & 31;
    const int j    = ((t >> 5) << 4) | (lane & 15);
    const int ks   = (lane >> 4) & 1;          // k-half AND batch owner
    const int b0   = blockIdx.x * 2;
    const int batch = b0 + ks;

    // Weights: 4 gates x 32 k-pairs (own k-half). 128 regs, shared across both batches.
    __half2 wi[32], wf[32], wo[32], wg[32];
#pragma unroll
    for (int q = 0; q < 32; q++) {
        const int kp = ks * 32 + q;
        wi[q] = g_wk[0 * 8192 + kp * 128 + j];
        wf[q] = g_wk[1 * 8192 + kp * 128 + j];
        wo[q] = g_wk[2 * 8192 + kp * 128 + j];
        wg[q] = g_wk[3 * 8192 + kp * 128 + j];
    }
    {
        float4* s_xw = reinterpret_cast<float4*>(sm);
#pragma unroll 4
        for (int i = t; i < FF * 128; i += NT) s_xw[i] = g_xw4[i];
    }
    const ulonglong2 bb = reinterpret_cast<const ulonglong2*>(g_bias4)[j];
    const ull bias_if_u = bb.x, bias_og_u = bb.y;

    const __half2 H_HALF = __floats2half2_rn(0.5f, 0.5f);
    const __half2 H_SM   = __floats2half2_rn(0.5f, 1.0f);
    const __half2 H_SB   = __floats2half2_rn(0.5f, 0.0f);

    float hB = 0.f, cB = 0.f, hS = 0.f, cS = 0.f, tcs = 0.f;
    int buf = 0;
    s_h16[t] = __float2half_rn(0.f);
    if (t < 16) s_h16[256 + t] = __float2half_rn(0.f);

    // prologue prefetch: x[0] (as fp32 splats) into s_xf[0], dt for sidx 0 into regs
    if (t < 128) {
        const float xv = x[(size_t)(b0 + (t >> 6)) * SS * FF + (t & 63)];
        s_xf2[((t & 63) << 1) | (t >> 6)] = make_float2(xv, xv);
    }
    float dtc = fminf(__ldg(&td[(size_t)batch * SS]), 1.0f) * 0.25f;
    __syncthreads();

#pragma unroll 1
    for (int sidx = 0; sidx < SS; sidx++) {
        const int xb = sidx & 1;
        const float dt  = dtc;
        const float dth = 0.5f * dt, dt6 = dt * (1.0f / 6.0f);

        // prefetch next timestep's x / dt (consumed next iteration; hidden by 16 evals)
        const int nidx = (sidx + 1 < SS) ? sidx + 1 : sidx;
        float xr = 0.f;
        if (t < 128)
            xr = x[(size_t)(b0 + (t >> 6)) * SS * FF + (size_t)nidx * FF + (t & 63)];
        const float dtn = fminf(__ldg(&td[(size_t)batch * SS + nidx]), 1.0f) * 0.25f;

        // pre = bias + x_t @ W_x — packed dual-fp32: 128 FFMA2, lanes = (gateA, gateB)
        ull aif0, aog0, aif1, aog1;
#pragma unroll
        for (int q = 0; q < 32; q++) {
            const int kk = ks * 32 + q;
            const ulonglong2 wv = s_xwu[kk * 128 + j];
            const ulonglong2 xv = s_xfu[xb * 64 + kk];
            if (q == 0) {
                MUL2(aif0, wv.x, xv.x); MUL2(aog0, wv.y, xv.x);
                MUL2(aif1, wv.x, xv.y); MUL2(aog1, wv.y, xv.y);
            } else {
                FMA2(aif0, wv.x, xv.x, aif0); FMA2(aog0, wv.y, xv.x, aog0);
                FMA2(aif1, wv.x, xv.y, aif1); FMA2(aog1, wv.y, xv.y, aog1);
            }
        }
        const ull own_if = ks ? aif1 : aif0, oth_if = ks ? aif0 : aif1;
        const ull own_og = ks ? aog1 : aog0, oth_og = ks ? aog0 : aog1;
        const ull rif = __shfl_xor_sync(0xffffffffu, oth_if, 16);
        const ull rog = __shfl_xor_sync(0xffffffffu, oth_og, 16);
        ull pif, pog;
        ADD2(pif, own_if, rif); ADD2(pif, pif, bias_if_u);
        ADD2(pog, own_og, rog); ADD2(pog, pog, bias_og_u);
        float p_i, p_f, p_o, p_g;
        asm("mov.b64 {%0,%1}, %2;" : "=f"(p_i), "=f"(p_f) : "l"(pif));
        asm("mov.b64 {%0,%1}, %2;" : "=f"(p_o), "=f"(p_g) : "l"(pog));
        // pre injected as chain initializer of each own-batch gate stream: (pre, 0) in fp16
        const __half2 ini_i = __floats2half2_rn(p_i, 0.f);
        const __half2 ini_f = __floats2half2_rn(p_f, 0.f);
        const __half2 ini_o = __floats2half2_rn(p_o, 0.f);
        const __half2 ini_g = __floats2half2_rn(p_g, 0.f);

#pragma unroll 1
        for (int sub = 0; sub < 4; sub++) {
            float accH = 0.f, accC = 0.f;
#pragma unroll
            for (int m = 0; m < 4; m++) {
                const __half* hb = s_h16 + buf * 272;
                const uint4* hpo = reinterpret_cast<const uint4*>(hb) + 25 * ks;        // own batch
                const uint4* hpx = reinterpret_cast<const uint4*>(hb) + (17 - 9 * ks);  // other batch

                // ---- MAC: 256 HFMA2, 16 LDS.128 (broadcast), prefetch distance 2 ----
                // ONE fp16 chain per stream (32 HFMA2 each); no per-stream reduction.
                uint4 ho[8], hx[8];
                ho[0] = hpo[0]; hx[0] = hpx[0];
                ho[1] = hpo[1]; hx[1] = hpx[1];
                __half2 aOi, aOf, aOo, aOg, aXi, aXf, aXo, aXg;
#pragma unroll
                for (int r = 0; r < 8; r++) {
                    if (r < 6) { ho[r + 2] = hpo[r + 2]; hx[r + 2] = hpx[r + 2]; }
                    const uint4 co = ho[r], cx = hx[r];
                    const __half2 e0[4] = {u2h2(co.x), u2h2(co.y), u2h2(co.z), u2h2(co.w)};
                    const __half2 e1[4] = {u2h2(cx.x), u2h2(cx.y), u2h2(cx.z), u2h2(cx.w)};
#pragma unroll
                    for (int q = 0; q < 4; q++) {
                        const int kp = r * 4 + q;
                        if (r == 0 && q == 0) {
                            aOi = __hfma2(e0[q], wi[kp], ini_i);   // chain carries pre (free)
                            aOf = __hfma2(e0[q], wf[kp], ini_f);
                            aOo = __hfma2(e0[q], wo[kp], ini_o);
                            aOg = __hfma2(e0[q], wg[kp], ini_g);
                            aXi = __hmul2(e1[q], wi[kp]);
                            aXf = __hmul2(e1[q], wf[kp]);
                            aXo = __hmul2(e1[q], wo[kp]);
                            aXg = __hmul2(e1[q], wg[kp]);
                        } else {
                            aOi = __hfma2(e0[q], wi[kp], aOi);
                            aOf = __hfma2(e0[q], wf[kp], aOf);
                            aOo = __hfma2(e0[q], wo[kp], aOo);
                            aOg = __hfma2(e0[q], wg[kp], aOg);
                            aXi = __hfma2(e1[q], wi[kp], aXi);
                            aXf = __hfma2(e1[q], wf[kp], aXf);
                            aXo = __hfma2(e1[q], wo[kp], aXo);
                            aXg = __hfma2(e1[q], wg[kp], aXg);
                        }
                    }
                }
                // (o,g) path FIRST — h-publish chain is barrier-critical
                const __half2 tog_x = pairsum(aXo, aXg);
                const unsigned e_og = __shfl_xor_sync(0xffffffffu, h2u(tog_x), 16);
                const __half2 tog_o = pairsum(aOo, aOg);           // includes pre
                const __half2 z_og  = __hadd2(tog_o, u2h2(e_og));
                const __half2 s_og  = __hfma2(tanh_h2(z_og), H_SM, H_SB);  // z pre-scaled

                const float so = __half2float(__low2half(s_og));
                const float kH = fmaf(so, tcs, -hS);              // dh = o*tanh(c) - h
                if (m == 0) accH = kH;
                else if (m == 3) accH += kH;
                else accH = fmaf(2.0f, kH, accH);
                if (m < 3) {
                    hS = fmaf((m < 2) ? dth : dt, kH, hB);
                } else {
                    hB = fmaf(dt6, accH, hB);
                    hS = hB;
                }
                s_h16[(buf ^ 1) * 272 + ks * 136 + j] = __float2half_rn(hS);   // earliest publish

                // (i,f) path — off the barrier-critical chain
                const __half2 tif_x = pairsum(aXi, aXf);
                const unsigned e_if = __shfl_xor_sync(0xffffffffu, h2u(tif_x), 16);
                const __half2 tif_o = pairsum(aOi, aOf);           // includes pre
                const __half2 z_if  = __hadd2(tif_o, u2h2(e_if));
                const __half2 s_if  = __hfma2(tanh_h2(z_if), H_HALF, H_HALF); // z pre-scaled

                const __half2 g2 = __high2half2(s_og);            // (g, g)
                const __half2 m2 = __hmul2(s_if, g2);             // (i*g, f*g)
                const float ig = __half2float(__low2half(m2));
                const float sf = __half2float(__high2half(s_if));

                const float kC = fmaf(sf, cS, ig - cS);           // dc = i*g + (f-1)*c
                if (m == 0) accC = kC;
                else if (m == 3) accC += kC;
                else accC = fmaf(2.0f, kC, accC);
                if (m < 3) {
                    cS = fmaf((m < 2) ? dth : dt, kC, cB);
                } else {
                    cB = fmaf(dt6, accC, cB);
                    cS = cB;
                }

                // last eval of the timestep also publishes next x splats (rides the same barrier)
                if (sub == 3 && m == 3 && t < 128)
                    s_xf2[((xb ^ 1) << 7) | ((t & 63) << 1) | (t >> 6)] = make_float2(xr, xr);

                buf ^= 1;
                __syncthreads();
                // post-barrier: tanh(c) for next eval hides under the next MAC issue
                tcs = tanh_ex(cS);
            }
        }
        dtc = dtn;
        out[(size_t)batch * SS * HH + (size_t)sidx * HH + j] = hB;
    }
}

extern "C" void kernel_launch(void* const* d_in, const int* in_sizes, int n_in,
                              void* d_out, int out_size) {
    const float* x  = (const float*)d_in[0];
    const float* td = (const float*)d_in[1];
    const float* Wi = (const float*)d_in[2];
    const float* bi = (const float*)d_in[3];
    const float* Wf = (const float*)d_in[4];
    const float* bf = (const float*)d_in[5];
    const float* Wo = (const float*)d_in[6];
    const float* bo = (const float*)d_in[7];
    const float* Wg = (const float*)d_in[8];
    const float* bg = (const float*)d_in[9];
    float* out = (float*)d_out;

    cudaFuncSetAttribute(clstm_kernel, cudaFuncAttributeMaxDynamicSharedMemorySize, SMEM_BYTES);

    pack_kernel<<<64, NT>>>(Wi, bi, Wf, bf, Wo, bo, Wg, bg);
    clstm_kernel<<<BB / 2, NT, SMEM_BYTES>>>(x, td, out);
}

// round 17
// speedup vs baseline: 1.0460x; 1.0460x over previous
#include <cuda_runtime.h>
#include <cuda_fp16.h>

#define BB 256
#define SS 512
#define FF 64
#define HH 128
#define NT 256

// Weights packed along k: g_wk[gate][kp][j] = half2(W[FF+2kp][j], W[FF+2kp+1][j])
// Gates i,f,o are PRE-SCALED by 0.5 (exact) so sigmoid args need no runtime mul.
__device__ __align__(16) __half2 g_wk[4 * 64 * 128];
__device__ __align__(8)  uint2   g_xwh[64 * 128];   // (k,j) -> (half2(.5wi,.5wf), half2(.5wo,wg))
__device__ __align__(8)  uint2   g_biash[128];      // j -> (half2(.5bi,.5bf), half2(.5bo,bg))

__device__ __forceinline__ unsigned h2u_(const __half2 h) { return *reinterpret_cast<const unsigned*>(&h); }

__global__ void pack_kernel(const float* __restrict__ Wi, const float* __restrict__ bi,
                            const float* __restrict__ Wf, const float* __restrict__ bf,
                            const float* __restrict__ Wo, const float* __restrict__ bo,
                            const float* __restrict__ Wg, const float* __restrict__ bg) {
    const int kp = blockIdx.x;       // 0..63 (k-pair)
    const int t  = threadIdx.x;
    const int j  = t & 127;
    const int pr = t >> 7;
    const int d0 = FF + 2 * kp, d1 = FF + 2 * kp + 1;
    if (pr == 0) {
        g_wk[0 * 8192 + kp * 128 + j] = __floats2half2_rn(0.5f * Wi[d0 * HH + j], 0.5f * Wi[d1 * HH + j]);
        g_wk[1 * 8192 + kp * 128 + j] = __floats2half2_rn(0.5f * Wf[d0 * HH + j], 0.5f * Wf[d1 * HH + j]);
        const __half2 xw_if = __floats2half2_rn(0.5f * Wi[kp * HH + j], 0.5f * Wf[kp * HH + j]);
        const __half2 xw_og = __floats2half2_rn(0.5f * Wo[kp * HH + j], Wg[kp * HH + j]);
        g_xwh[kp * 128 + j] = make_uint2(h2u_(xw_if), h2u_(xw_og));
    } else {
        g_wk[2 * 8192 + kp * 128 + j] = __floats2half2_rn(0.5f * Wo[d0 * HH + j], 0.5f * Wo[d1 * HH + j]);
        g_wk[3 * 8192 + kp * 128 + j] = __floats2half2_rn(Wg[d0 * HH + j], Wg[d1 * HH + j]);
        if (kp == 0) {
            const __half2 b_if = __floats2half2_rn(0.5f * bi[j], 0.5f * bf[j]);
            const __half2 b_og = __floats2half2_rn(0.5f * bo[j], bg[j]);
            g_biash[j] = make_uint2(h2u_(b_if), h2u_(b_og));
        }
    }
}

__device__ __forceinline__ float fast_ex2(float a) { float r; asm("ex2.approx.f32 %0, %1;" : "=f"(r) : "f"(a)); return r; }
__device__ __forceinline__ float fast_rcp(float a) { float r; asm("rcp.approx.f32 %0, %1;" : "=f"(r) : "f"(a)); return r; }
__device__ __forceinline__ float tanh_ex(float x) { return fmaf(-2.0f, fast_rcp(1.0f + fast_ex2(2.8853900817779268f * x)), 1.0f); }

__device__ __forceinline__ __half2 u2h2(unsigned u) { __half2 r; *reinterpret_cast<unsigned*>(&r) = u; return r; }
__device__ __forceinline__ unsigned h2u(__half2 h) { return *reinterpret_cast<unsigned*>(&h); }
__device__ __forceinline__ __half2 tanh_h2(__half2 a) {
    unsigned r, x = h2u(a);
    asm("tanh.approx.f16x2 %0, %1;" : "=r"(r) : "r"(x));
    return u2h2(r);
}
// half2(lo a + hi a, lo b + hi b): 2 PRMT (alu pipe) + 1 HADD2
__device__ __forceinline__ __half2 pairsum(__half2 a, __half2 b) {
    const unsigned lo = __byte_perm(h2u(a), h2u(b), 0x5410);
    const unsigned hi = __byte_perm(h2u(a), h2u(b), 0x7632);
    return __hadd2(u2h2(lo), u2h2(hi));
}
__device__ __forceinline__ __half2 red4h(const __half2* a) {
    return __hadd2(__hadd2(a[0], a[1]), __hadd2(a[2], a[3]));
}

// Smem: [0,65536) uint2 s_xwh | [65536,+1088) half s_h16[2 buf] | [66624,+1024) uint s_x2[2 buf][64k][2b]
#define SMH_OFF 65536
#define SX2_OFF 66624
#define SMEM_BYTES (66624 + 1024)

__global__ void __launch_bounds__(NT, 1)
clstm_kernel(const float* __restrict__ x, const float* __restrict__ td, float* __restrict__ out) {
    extern __shared__ char sm[];
    uint2*  s_xwh = reinterpret_cast<uint2*>(sm);
    __half* s_h16 = reinterpret_cast<__half*>(sm + SMH_OFF);
    unsigned* s_x2 = reinterpret_cast<unsigned*>(sm + SX2_OFF);   // [2 buf][64 k][2 b]

    const int t    = threadIdx.x;
    const int lane = t & 31;
    const int j    = ((t >> 5) << 4) | (lane & 15);
    const int ks   = (lane >> 4) & 1;          // k-half AND batch owner
    const int b0   = blockIdx.x * 2;
    const int batch = b0 + ks;

    // Weights: 4 gates x 32 k-pairs (own k-half). 128 regs, shared across both batches.
    __half2 wi[32], wf[32], wo[32], wg[32];
#pragma unroll
    for (int q = 0; q < 32; q++) {
        const int kp = ks * 32 + q;
        wi[q] = g_wk[0 * 8192 + kp * 128 + j];
        wf[q] = g_wk[1 * 8192 + kp * 128 + j];
        wo[q] = g_wk[2 * 8192 + kp * 128 + j];
        wg[q] = g_wk[3 * 8192 + kp * 128 + j];
    }
#pragma unroll 4
    for (int i = t; i < FF * 128; i += NT) s_xwh[i] = g_xwh[i];
    const uint2 bh = g_biash[j];
    const __half2 bias_if = u2h2(bh.x), bias_og = u2h2(bh.y);

    const __half2 H_HALF = __floats2half2_rn(0.5f, 0.5f);

    float hB = 0.f, cB = 0.f, hS = 0.f, cS = 0.f;
    float Af = 0.f, Bf = 0.f;   // kH = tanh(z_o/2)*Af + Bf ; Af=0.5*tanh(c), Bf=Af-hS
    int buf = 0;
    s_h16[t] = __float2half_rn(0.f);
    if (t < 16) s_h16[256 + t] = __float2half_rn(0.f);

    // prologue prefetch: x[0] (as half2 splats) into s_x2[0], dt for sidx 0 into regs
    if (t < 128) {
        const float xv = x[(size_t)(b0 + (t >> 6)) * SS * FF + (t & 63)];
        s_x2[((t & 63) << 1) | (t >> 6)] = h2u(__half2half2(__float2half_rn(xv)));
    }
    float dtc = fminf(__ldg(&td[(size_t)batch * SS]), 1.0f) * 0.25f;
    __syncthreads();

#pragma unroll 1
    for (int sidx = 0; sidx < SS; sidx++) {
        const int xb = sidx & 1;
        const float dt  = dtc;
        const float dth = 0.5f * dt, dt6 = dt * (1.0f / 6.0f);

        // prefetch next timestep's x / dt (consumed next iteration; hidden by 16 evals)
        const int nidx = (sidx + 1 < SS) ? sidx + 1 : sidx;
        float xr = 0.f;
        if (t < 128)
            xr = x[(size_t)(b0 + (t >> 6)) * SS * FF + (size_t)nidx * FF + (t & 63)];
        const float dtn = fminf(__ldg(&td[(size_t)batch * SS + nidx]), 1.0f) * 0.25f;

        // pre = bias + x_t @ W_x — fp16 half2: 128 HFMA2 in 4 chains of 8 per stream
        const uint2* x2 = reinterpret_cast<const uint2*>(s_x2) + xb * 64;
        __half2 pif0[4], pog0[4], pif1[4], pog1[4];
#pragma unroll
        for (int q = 0; q < 32; q++) {
            const int kk = ks * 32 + q;
            const uint2 wv = s_xwh[kk * 128 + j];
            const uint2 xv = x2[kk];
            const __half2 w_if = u2h2(wv.x), w_og = u2h2(wv.y);
            const __half2 x_0 = u2h2(xv.x), x_1 = u2h2(xv.y);
            const int ch = q & 3;
            if (q < 4) {
                pif0[ch] = __hmul2(x_0, w_if); pog0[ch] = __hmul2(x_0, w_og);
                pif1[ch] = __hmul2(x_1, w_if); pog1[ch] = __hmul2(x_1, w_og);
            } else {
                pif0[ch] = __hfma2(x_0, w_if, pif0[ch]); pog0[ch] = __hfma2(x_0, w_og, pog0[ch]);
                pif1[ch] = __hfma2(x_1, w_if, pif1[ch]); pog1[ch] = __hfma2(x_1, w_og, pog1[ch]);
            }
        }
        const __half2 rif0 = red4h(pif0), rog0 = red4h(pog0);
        const __half2 rif1 = red4h(pif1), rog1 = red4h(pog1);
        const __half2 own_if = ks ? rif1 : rif0, oth_if = ks ? rif0 : rif1;
        const __half2 own_og = ks ? rog1 : rog0, oth_og = ks ? rog0 : rog1;
        const unsigned eifx = __shfl_xor_sync(0xffffffffu, h2u(oth_if), 16);
        const unsigned eogx = __shfl_xor_sync(0xffffffffu, h2u(oth_og), 16);
        const __half2 pre_if = __hadd2(__hadd2(own_if, u2h2(eifx)), bias_if);
        const __half2 pre_og = __hadd2(__hadd2(own_og, u2h2(eogx)), bias_og);
        // pre injected as chain initializer of each own-batch gate stream: (pre, 0) via PRMT
        const __half2 ini_i = u2h2(__byte_perm(h2u(pre_if), 0, 0x4410));
        const __half2 ini_f = u2h2(__byte_perm(h2u(pre_if), 0, 0x4432));
        const __half2 ini_o = u2h2(__byte_perm(h2u(pre_og), 0, 0x4410));
        const __half2 ini_g = u2h2(__byte_perm(h2u(pre_og), 0, 0x4432));

#pragma unroll 1
        for (int sub = 0; sub < 4; sub++) {
            float accH = 0.f, accC = 0.f;
#pragma unroll
            for (int m = 0; m < 4; m++) {
                const __half* hb = s_h16 + buf * 272;
                const uint4* hpo = reinterpret_cast<const uint4*>(hb) + 25 * ks;        // own batch
                const uint4* hpx = reinterpret_cast<const uint4*>(hb) + (17 - 9 * ks);  // other batch

                // ---- MAC: 256 HFMA2, 16 LDS.128 (broadcast), prefetch distance 2 ----
                // ONE fp16 chain per stream (32 HFMA2 each); no per-stream reduction.
                uint4 ho[8], hx[8];
                ho[0] = hpo[0]; hx[0] = hpx[0];
                ho[1] = hpo[1]; hx[1] = hpx[1];
                __half2 aOi, aOf, aOo, aOg, aXi, aXf, aXo, aXg;
#pragma unroll
                for (int r = 0; r < 8; r++) {
                    if (r < 6) { ho[r + 2] = hpo[r + 2]; hx[r + 2] = hpx[r + 2]; }
                    const uint4 co = ho[r], cx = hx[r];
                    const __half2 e0[4] = {u2h2(co.x), u2h2(co.y), u2h2(co.z), u2h2(co.w)};
                    const __half2 e1[4] = {u2h2(cx.x), u2h2(cx.y), u2h2(cx.z), u2h2(cx.w)};
#pragma unroll
                    for (int q = 0; q < 4; q++) {
                        const int kp = r * 4 + q;
                        if (r == 0 && q == 0) {
                            aOi = __hfma2(e0[q], wi[kp], ini_i);   // chain carries pre (free)
                            aOf = __hfma2(e0[q], wf[kp], ini_f);
                            aOo = __hfma2(e0[q], wo[kp], ini_o);
                            aOg = __hfma2(e0[q], wg[kp], ini_g);
                            aXi = __hmul2(e1[q], wi[kp]);
                            aXf = __hmul2(e1[q], wf[kp]);
                            aXo = __hmul2(e1[q], wo[kp]);
                            aXg = __hmul2(e1[q], wg[kp]);
                        } else {
                            aOi = __hfma2(e0[q], wi[kp], aOi);
                            aOf = __hfma2(e0[q], wf[kp], aOf);
                            aOo = __hfma2(e0[q], wo[kp], aOo);
                            aOg = __hfma2(e0[q], wg[kp], aOg);
                            aXi = __hfma2(e1[q], wi[kp], aXi);
                            aXf = __hfma2(e1[q], wf[kp], aXf);
                            aXo = __hfma2(e1[q], wo[kp], aXo);
                            aXg = __hfma2(e1[q], wg[kp], aXg);
                        }
                    }
                }
                // (o,g) path FIRST — h-publish chain is barrier-critical.
                // kH = tanh(z_o/2)*Af + Bf  (Af/Bf precomputed post-barrier last eval);
                // the g lane of th2 is already tanh(z_g) (identity scaling) — s_og HFMA2 deleted.
                const __half2 tog_x = pairsum(aXo, aXg);
                const unsigned e_og = __shfl_xor_sync(0xffffffffu, h2u(tog_x), 16);
                const __half2 tog_o = pairsum(aOo, aOg);           // includes pre
                const __half2 z_og  = __hadd2(tog_o, u2h2(e_og));
                const __half2 th2   = tanh_h2(z_og);               // (tanh(.5 z_o), g)

                const float th_o = __half2float(__low2half(th2));
                const float kH = fmaf(th_o, Af, Bf);               // == o*tanh(c) - h
                if (m == 0) accH = kH;
                else if (m == 3) accH += kH;
                else accH = fmaf(2.0f, kH, accH);
                if (m < 3) {
                    hS = fmaf((m < 2) ? dth : dt, kH, hB);
                } else {
                    hB = fmaf(dt6, accH, hB);
                    hS = hB;
                }
                s_h16[(buf ^ 1) * 272 + ks * 136 + j] = __float2half_rn(hS);   // earliest publish

                // (i,f) path — off the barrier-critical chain
                const __half2 tif_x = pairsum(aXi, aXf);
                const unsigned e_if = __shfl_xor_sync(0xffffffffu, h2u(tif_x), 16);
                const __half2 tif_o = pairsum(aOi, aOf);           // includes pre
                const __half2 z_if  = __hadd2(tif_o, u2h2(e_if));
                const __half2 s_if  = __hfma2(tanh_h2(z_if), H_HALF, H_HALF); // z pre-scaled

                const __half2 g2 = __high2half2(th2);              // (g, g)
                const __half2 m2 = __hmul2(s_if, g2);              // (i*g, f*g)
                const float ig = __half2float(__low2half(m2));
                const float sf = __half2float(__high2half(s_if));

                const float kC = fmaf(sf, cS, ig - cS);            // dc = i*g + (f-1)*c
                if (m == 0) accC = kC;
                else if (m == 3) accC += kC;
                else accC = fmaf(2.0f, kC, accC);
                if (m < 3) {
                    cS = fmaf((m < 2) ? dth : dt, kC, cB);
                } else {
                    cB = fmaf(dt6, accC, cB);
                    cS = cB;
                }

                // last eval of the timestep also publishes next x (rides the same barrier)
                if (sub == 3 && m == 3 && t < 128)
                    s_x2[((xb ^ 1) << 7) | ((t & 63) << 1) | (t >> 6)] =
                        h2u(__half2half2(__float2half_rn(xr)));

                buf ^= 1;
                __syncthreads();
                // post-barrier: tanh(c) + kH coefficients for next eval; hides under next MAC
                const float tcs = tanh_ex(cS);
                Af = 0.5f * tcs;
                Bf = Af - hS;
            }
        }
        dtc = dtn;
        out[(size_t)batch * SS * HH + (size_t)sidx * HH + j] = hB;
    }
}

extern "C" void kernel_launch(void* const* d_in, const int* in_sizes, int n_in,
                              void* d_out, int out_size) {
    const float* x  = (const float*)d_in[0];
    const float* td = (const float*)d_in[1];
    const float* Wi = (const float*)d_in[2];
    const float* bi = (const float*)d_in[3];
    const float* Wf = (const float*)d_in[4];
    const float* bf = (const float*)d_in[5];
    const float* Wo = (const float*)d_in[6];
    const float* bo = (const float*)d_in[7];
    const float* Wg = (const float*)d_in[8];
    const float* bg = (const float*)d_in[9];
    float* out = (float*)d_out;

    cudaFuncSetAttribute(clstm_kernel, cudaFuncAttributeMaxDynamicSharedMemorySize, SMEM_BYTES);

    pack_kernel<<<64, NT>>>(Wi, bi, Wf, bf, Wo, bo, Wg, bg);
    clstm_kernel<<<BB / 2, NT, SMEM_BYTES>>>(x, td, out);
}